// round 5
// baseline (speedup 1.0000x reference)
#include <cuda_runtime.h>
#include <cuda_fp16.h>
#include <cstdint>

// ---------------- problem constants ----------------
#define BM 128
#define BN 256
#define BK 64
#define KH 2048
#define NTOK 4096            // B*T
#define VSZ 32000
#define NVT (VSZ / BN)       // 125
#define NSLICE (NVT * 4)     // 500: each warp-n quarter writes its own partial
#define NIT (KH / BK)        // 32
#define NSTAGE 4

// ---------------- device scratch (no allocs allowed) ----------------
__device__ __half g_w[(size_t)VSZ * KH];           // 128 MB fp16 weights
__device__ __half g_a[(size_t)NTOK * KH];          // 16 MB fp16 activations
__device__ float g_pmax[(size_t)NSLICE * NTOK];    // per (slice, token) max
__device__ float g_psum[(size_t)NSLICE * NTOK];    // per (slice, token) sumexp
__device__ float g_tgt[NTOK];                      // exact target logit (fp32)
__device__ int   g_tgti[NTOK];                     // decoded target indices
__device__ float g_avg[8];                         // per-sequence avg logp

// ---------------- smem layout ----------------
#define A_STG (BM * 128)                 // 16384 B (128 rows x 128B)
#define B_STG (BN * 128)                 // 32768 B (256 rows x 128B)
#define STG   (A_STG + B_STG)            // 49152 B per stage
#define SMEM_BYTES (NSTAGE * STG)        // 196608 B -> 1 CTA/SM

// ---------------- helpers ----------------
__device__ __forceinline__ uint32_t smem_u32(const void* p) {
    uint32_t a;
    asm("{ .reg .u64 t; cvta.to.shared.u64 t, %1; cvt.u32.u64 %0, t; }" : "=r"(a) : "l"(p));
    return a;
}
__device__ __forceinline__ uint32_t sw128(uint32_t off) { return off ^ ((off >> 3) & 0x70); }

__device__ __forceinline__ void cp16(uint32_t s, const void* g) {
    asm volatile("cp.async.cg.shared.global [%0], [%1], 16;" :: "r"(s), "l"(g) : "memory");
}
__device__ __forceinline__ void cp_commit() { asm volatile("cp.async.commit_group;" ::: "memory"); }

__device__ __forceinline__ void ldsm4(uint32_t* r, uint32_t addr) {
    asm volatile("ldmatrix.sync.aligned.m8n8.x4.shared.b16 {%0,%1,%2,%3}, [%4];"
                 : "=r"(r[0]), "=r"(r[1]), "=r"(r[2]), "=r"(r[3]) : "r"(addr));
}
__device__ __forceinline__ void mma16816(float* c, const uint32_t* a, const uint32_t* b) {
    asm volatile("mma.sync.aligned.m16n8k16.row.col.f32.f16.f16.f32 "
                 "{%0,%1,%2,%3}, {%4,%5,%6,%7}, {%8,%9}, {%0,%1,%2,%3};"
                 : "+f"(c[0]), "+f"(c[1]), "+f"(c[2]), "+f"(c[3])
                 : "r"(a[0]), "r"(a[1]), "r"(a[2]), "r"(a[3]), "r"(b[0]), "r"(b[1]));
}

// ---------------- target dtype decoder (int32 vs int64, data-driven) --------
__global__ void __launch_bounds__(1024) tgt_decode_kernel(const int* __restrict__ t32) {
    __shared__ int s_is64;
    if (threadIdx.x == 0) s_is64 = 1;
    __syncthreads();
    int ok64 = 1;
    #pragma unroll
    for (int j = 0; j < 4; j++) {
        const int i = threadIdx.x + j * 1024;          // probe first 4096 words (16 KB, safe)
        const int v = t32[i];
        if (i & 1) { if (v != 0 && v != -1) ok64 = 0; }
        else       { if (!(v == -100 || (v >= 0 && v < VSZ))) ok64 = 0; }
    }
    if (!ok64) s_is64 = 0;
    __syncthreads();
    const int is64 = s_is64;
    #pragma unroll
    for (int j = 0; j < 4; j++) {
        const int i = threadIdx.x + j * 1024;
        g_tgti[i] = is64 ? t32[2 * i] : t32[i];
    }
}

// ---------------- fp32 -> fp16 converts ----------------
__device__ __forceinline__ unsigned pk2(float lo, float hi) {
    __half2 t = __floats2half2_rn(lo, hi);
    return *reinterpret_cast<unsigned*>(&t);
}
__global__ void cvt_w_kernel(const float4* __restrict__ src) {
    int i = blockIdx.x * blockDim.x + threadIdx.x;     // 8 elems per thread
    if (i >= (int)((size_t)VSZ * KH / 8)) return;
    float4 a = src[2 * i], b = src[2 * i + 1];
    uint4 o;
    o.x = pk2(a.x, a.y); o.y = pk2(a.z, a.w);
    o.z = pk2(b.x, b.y); o.w = pk2(b.z, b.w);
    reinterpret_cast<uint4*>(g_w)[i] = o;
}
__global__ void cvt_a_kernel(const float4* __restrict__ src) {
    int i = blockIdx.x * blockDim.x + threadIdx.x;
    if (i >= (int)((size_t)NTOK * KH / 8)) return;
    float4 a = src[2 * i], b = src[2 * i + 1];
    uint4 o;
    o.x = pk2(a.x, a.y); o.y = pk2(a.z, a.w);
    o.z = pk2(b.x, b.y); o.w = pk2(b.z, b.w);
    reinterpret_cast<uint4*>(g_a)[i] = o;
}

// ---------------- exact fp32 target logit per token ----------------
__global__ void __launch_bounds__(128) tgt_kernel(
    const float* __restrict__ weight, const float* __restrict__ input,
    const float* __restrict__ bias) {
    const int token = blockIdx.x;
    const int tg = g_tgti[token];
    if (tg == -100) { if (threadIdx.x == 0) g_tgt[token] = 0.f; return; }
    const float4* a = reinterpret_cast<const float4*>(input + (size_t)token * KH);
    const float4* w = reinterpret_cast<const float4*>(weight + (size_t)tg * KH);
    float s = 0.f;
    #pragma unroll
    for (int j = 0; j < 4; j++) {
        const int i = threadIdx.x + j * 128;       // 512 float4 total
        float4 av = a[i], wv = w[i];
        s += av.x * wv.x + av.y * wv.y + av.z * wv.z + av.w * wv.w;
    }
    #pragma unroll
    for (int o = 16; o > 0; o >>= 1) s += __shfl_xor_sync(0xffffffffu, s, o);
    __shared__ float ws[4];
    if ((threadIdx.x & 31) == 0) ws[threadIdx.x >> 5] = s;
    __syncthreads();
    if (threadIdx.x == 0)
        g_tgt[token] = ws[0] + ws[1] + ws[2] + ws[3] + bias[tg];
}

// ---------------- fused GEMM + partial softmax ----------------
// 128x256 CTA tile, 8 warps of 64x64, 4-stage cp.async pipeline, 1 CTA/SM.
__global__ void __launch_bounds__(256, 1) gemm_softmax_kernel(
    const float* __restrict__ bias) {
    extern __shared__ char smem[];
    const uint32_t sbase = smem_u32(smem);
    const int tid = threadIdx.x;
    const int lane = tid & 31;
    const int warp = tid >> 5;
    const int wm = warp >> 2;          // 0..1  (m slice of 64 rows)
    const int wn = warp & 3;           // 0..3  (n slice of 64 cols)
    const int m0 = blockIdx.x * BM;
    const int v0 = blockIdx.y * BN;

    // stage loader: fills slot (it & 3) with K-slice `it`
    auto load_stage = [&](int it) {
        const int st = it & (NSTAGE - 1);
        const int k0 = it * BK;
        const uint32_t sA = sbase + st * STG;
        const __half* ab = g_a + (size_t)m0 * KH + k0;
        #pragma unroll
        for (int j = 0; j < 4; j++) {            // 128 rows x 8 segs / 256 thr
            int id = tid + j * 256;
            int row = id >> 3, seg = id & 7;
            cp16(sA + sw128(row * 128 + seg * 16), ab + (size_t)row * KH + seg * 8);
        }
        const uint32_t sB = sA + A_STG;
        const __half* bb = g_w + (size_t)v0 * KH + k0;
        #pragma unroll
        for (int j = 0; j < 8; j++) {            // 256 rows x 8 segs / 256 thr
            int id = tid + j * 256;
            int row = id >> 3, seg = id & 7;
            cp16(sB + sw128(row * 128 + seg * 16), bb + (size_t)row * KH + seg * 8);
        }
    };

    load_stage(0); cp_commit();
    load_stage(1); cp_commit();
    load_stage(2); cp_commit();

    float acc[4][8][4];
    #pragma unroll
    for (int mt = 0; mt < 4; mt++)
        #pragma unroll
        for (int nt = 0; nt < 8; nt++)
            #pragma unroll
            for (int r = 0; r < 4; r++) acc[mt][nt][r] = 0.f;

    // per-lane ldmatrix base byte offsets (within tile, before swizzle)
    uint32_t aoff[4], boff[4];
    #pragma unroll
    for (int mt = 0; mt < 4; mt++)
        aoff[mt] = (uint32_t)(wm * 64 + mt * 16 + (lane & 7) + ((lane >> 3) & 1) * 8) * 128
                 + ((lane >> 4) & 1) * 16;
    #pragma unroll
    for (int np = 0; np < 4; np++)      // pair of n8-tiles (16 B-rows)
        boff[np] = (uint32_t)(wn * 64 + np * 16 + ((lane >> 4) & 1) * 8 + (lane & 7)) * 128
                 + ((lane >> 3) & 1) * 16;

    for (int it = 0; it < NIT; ++it) {
        asm volatile("cp.async.wait_group 2;" ::: "memory");
        __syncthreads();
        if (it + 3 < NIT) load_stage(it + 3);
        cp_commit();

        const uint32_t sA = sbase + (it & (NSTAGE - 1)) * STG;
        const uint32_t sB = sA + A_STG;
        #pragma unroll
        for (int ks = 0; ks < 4; ks++) {
            uint32_t a[4][4], b[4][4];
            #pragma unroll
            for (int mt = 0; mt < 4; mt++) ldsm4(a[mt], sA + sw128(aoff[mt] + ks * 32));
            #pragma unroll
            for (int np = 0; np < 4; np++) ldsm4(b[np], sB + sw128(boff[np] + ks * 32));
            #pragma unroll
            for (int mt = 0; mt < 4; mt++)
                #pragma unroll
                for (int nt = 0; nt < 8; nt++)
                    mma16816(acc[mt][nt], a[mt], b[nt >> 1] + (nt & 1) * 2);
        }
    }

    // ---------------- epilogue: fused partial softmax ----------------
    asm volatile("cp.async.wait_group 0;" ::: "memory");
    __syncthreads();
    float* sbias = reinterpret_cast<float*>(smem);
    sbias[tid] = bias[v0 + tid];
    __syncthreads();

    const int slice = blockIdx.y * 4 + wn;
    const int cbase = wn * 64 + (lane & 3) * 2;      // local col of reg j=0

    #pragma unroll
    for (int mt = 0; mt < 4; mt++) {
        #pragma unroll
        for (int half = 0; half < 2; half++) {
            const int row = wm * 64 + mt * 16 + (lane >> 2) + half * 8;
            const int token = m0 + row;
            float x[16];
            float M = -3.402823466e38f;
            #pragma unroll
            for (int nt = 0; nt < 8; nt++) {
                x[2 * nt]     = acc[mt][nt][2 * half]     + sbias[cbase + nt * 8];
                x[2 * nt + 1] = acc[mt][nt][2 * half + 1] + sbias[cbase + nt * 8 + 1];
                M = fmaxf(M, fmaxf(x[2 * nt], x[2 * nt + 1]));
            }
            M = fmaxf(M, __shfl_xor_sync(0xffffffffu, M, 1));
            M = fmaxf(M, __shfl_xor_sync(0xffffffffu, M, 2));
            float S = 0.f;
            #pragma unroll
            for (int j = 0; j < 16; j++) S += __expf(x[j] - M);
            S += __shfl_xor_sync(0xffffffffu, S, 1);
            S += __shfl_xor_sync(0xffffffffu, S, 2);
            if ((lane & 3) == 0) {
                g_pmax[(size_t)slice * NTOK + token] = M;
                g_psum[(size_t)slice * NTOK + token] = S;
            }
        }
    }
}

// ---------------- per-sequence LSE combine + avg logp ----------------
__global__ void reduce_kernel() {
    __shared__ float rs[512];
    __shared__ float rc[512];
    const int seq = blockIdx.x, t = threadIdx.x;
    const int token = seq * 512 + t;
    const int tg = g_tgti[token];
    float val = 0.f, cnt = 0.f;
    if (tg != -100) {
        float M = -3.402823466e38f, S = 0.f;
        #pragma unroll 4
        for (int sl = 0; sl < NSLICE; sl++) {
            const float mv = g_pmax[(size_t)sl * NTOK + token];
            const float sv = g_psum[(size_t)sl * NTOK + token];
            const float nm = fmaxf(M, mv);
            S = S * __expf(M - nm) + sv * __expf(mv - nm);
            M = nm;
        }
        val = g_tgt[token] - (M + __logf(S));
        cnt = 1.f;
    }
    rs[t] = val; rc[t] = cnt;
    __syncthreads();
    for (int o = 256; o > 0; o >>= 1) {
        if (t < o) { rs[t] += rs[t + o]; rc[t] += rc[t + o]; }
        __syncthreads();
    }
    if (t == 0) g_avg[seq] = rs[0] / fmaxf(rc[0], 1.f);
}

// ---------------- SimPO pair loss ----------------
__global__ void finalize_kernel(float* __restrict__ out) {
    if (threadIdx.x == 0 && blockIdx.x == 0) {
        float loss = 0.f;
        #pragma unroll
        for (int i = 0; i < 4; i++) {
            const float d = 0.1f * (g_avg[i] - g_avg[i + 4]) - 0.5f;
            const float xm = -d;  // -log_sigmoid(d) = softplus(-d)
            loss += (xm > 0.f) ? (xm + log1pf(expf(-xm))) : log1pf(expf(xm));
        }
        out[0] = loss * 0.25f;
    }
}

// ---------------- launch ----------------
extern "C" void kernel_launch(void* const* d_in, const int* in_sizes, int n_in,
                              void* d_out, int out_size) {
    const float* lin_weight = (const float*)d_in[0];       // [V, H]
    const float* input      = (const float*)d_in[1];       // [B, T, H]
    const int*   target_raw = (const int*)d_in[2];         // [B, T] int32 or int64
    const float* bias       = (const float*)d_in[3];       // [V]

    cudaFuncSetAttribute(gemm_softmax_kernel,
                         cudaFuncAttributeMaxDynamicSharedMemorySize, SMEM_BYTES);

    tgt_decode_kernel<<<1, 1024>>>(target_raw);
    cvt_w_kernel<<<(int)((size_t)VSZ * KH / 8 / 256), 256>>>((const float4*)lin_weight);
    cvt_a_kernel<<<(int)((size_t)NTOK * KH / 8 / 256), 256>>>((const float4*)input);
    tgt_kernel<<<NTOK, 128>>>(lin_weight, input, bias);

    dim3 grid(NTOK / BM, NVT);   // x-fastest => 32 M-CTAs share each W tile in L2
    gemm_softmax_kernel<<<grid, 256, SMEM_BYTES>>>(bias);

    reduce_kernel<<<8, 512>>>();
    finalize_kernel<<<1, 32>>>((float*)d_out);
}

// round 6
// speedup vs baseline: 1.1280x; 1.1280x over previous
#include <cuda_runtime.h>
#include <cuda_fp16.h>
#include <cstdint>

// ---------------- problem constants ----------------
#define BM 128
#define BN 128
#define BK 64
#define KH 2048
#define NTOK 4096            // B*T
#define VSZ 32000
#define NVT (VSZ / BN)       // 250
#define NSLICE (NVT * 2)     // 500: each warp-n half writes its own partial
#define NIT (KH / BK)        // 32
#define NSTAGE 3

// ---------------- device scratch (no allocs allowed) ----------------
__device__ __half g_w[(size_t)VSZ * KH];           // 128 MB fp16 weights
__device__ __half g_a[(size_t)NTOK * KH];          // 16 MB fp16 activations
__device__ float g_pmax[(size_t)NSLICE * NTOK];    // per (slice, token) max
__device__ float g_psum[(size_t)NSLICE * NTOK];    // per (slice, token) sumexp
__device__ float g_tgt[NTOK];                      // exact target logit (fp32)
__device__ int   g_tgti[NTOK];                     // decoded target indices
__device__ float g_avg[8];                         // per-sequence avg logp

// ---------------- smem layout ----------------
#define A_STG (BM * 128)                 // 16384 B (128 rows x 128B)
#define B_STG (BN * 128)                 // 16384 B
#define STG   (A_STG + B_STG)            // 32768 B per stage
#define SMEM_BYTES (NSTAGE * STG)        // 98304 B -> 2 CTAs/SM

// ---------------- helpers ----------------
__device__ __forceinline__ uint32_t smem_u32(const void* p) {
    uint32_t a;
    asm("{ .reg .u64 t; cvta.to.shared.u64 t, %1; cvt.u32.u64 %0, t; }" : "=r"(a) : "l"(p));
    return a;
}
__device__ __forceinline__ uint32_t sw128(uint32_t off) { return off ^ ((off >> 3) & 0x70); }

__device__ __forceinline__ void cp16(uint32_t s, const void* g) {
    asm volatile("cp.async.cg.shared.global [%0], [%1], 16;" :: "r"(s), "l"(g) : "memory");
}
__device__ __forceinline__ void cp_commit() { asm volatile("cp.async.commit_group;" ::: "memory"); }

__device__ __forceinline__ void ldsm4(uint32_t* r, uint32_t addr) {
    asm volatile("ldmatrix.sync.aligned.m8n8.x4.shared.b16 {%0,%1,%2,%3}, [%4];"
                 : "=r"(r[0]), "=r"(r[1]), "=r"(r[2]), "=r"(r[3]) : "r"(addr));
}
__device__ __forceinline__ void mma16816(float* c, const uint32_t* a, const uint32_t* b) {
    asm volatile("mma.sync.aligned.m16n8k16.row.col.f32.f16.f16.f32 "
                 "{%0,%1,%2,%3}, {%4,%5,%6,%7}, {%8,%9}, {%0,%1,%2,%3};"
                 : "+f"(c[0]), "+f"(c[1]), "+f"(c[2]), "+f"(c[3])
                 : "r"(a[0]), "r"(a[1]), "r"(a[2]), "r"(a[3]), "r"(b[0]), "r"(b[1]));
}

// ---------------- target dtype decoder (int32 vs int64, data-driven) --------
__global__ void __launch_bounds__(1024) tgt_decode_kernel(const int* __restrict__ t32) {
    __shared__ int s_is64;
    if (threadIdx.x == 0) s_is64 = 1;
    __syncthreads();
    int ok64 = 1;
    #pragma unroll
    for (int j = 0; j < 4; j++) {
        const int i = threadIdx.x + j * 1024;          // probe first 4096 words (16 KB, safe)
        const int v = t32[i];
        if (i & 1) { if (v != 0 && v != -1) ok64 = 0; }
        else       { if (!(v == -100 || (v >= 0 && v < VSZ))) ok64 = 0; }
    }
    if (!ok64) s_is64 = 0;
    __syncthreads();
    const int is64 = s_is64;
    #pragma unroll
    for (int j = 0; j < 4; j++) {
        const int i = threadIdx.x + j * 1024;
        g_tgti[i] = is64 ? t32[2 * i] : t32[i];
    }
}

// ---------------- fp32 -> fp16 converts ----------------
__device__ __forceinline__ unsigned pk2(float lo, float hi) {
    __half2 t = __floats2half2_rn(lo, hi);
    return *reinterpret_cast<unsigned*>(&t);
}
__global__ void cvt_w_kernel(const float4* __restrict__ src) {
    int i = blockIdx.x * blockDim.x + threadIdx.x;     // 8 elems per thread
    if (i >= (int)((size_t)VSZ * KH / 8)) return;
    float4 a = src[2 * i], b = src[2 * i + 1];
    uint4 o;
    o.x = pk2(a.x, a.y); o.y = pk2(a.z, a.w);
    o.z = pk2(b.x, b.y); o.w = pk2(b.z, b.w);
    reinterpret_cast<uint4*>(g_w)[i] = o;
}
__global__ void cvt_a_kernel(const float4* __restrict__ src) {
    int i = blockIdx.x * blockDim.x + threadIdx.x;
    if (i >= (int)((size_t)NTOK * KH / 8)) return;
    float4 a = src[2 * i], b = src[2 * i + 1];
    uint4 o;
    o.x = pk2(a.x, a.y); o.y = pk2(a.z, a.w);
    o.z = pk2(b.x, b.y); o.w = pk2(b.z, b.w);
    reinterpret_cast<uint4*>(g_a)[i] = o;
}

// ---------------- exact fp32 target logit per token ----------------
__global__ void __launch_bounds__(128) tgt_kernel(
    const float* __restrict__ weight, const float* __restrict__ input,
    const float* __restrict__ bias) {
    const int token = blockIdx.x;
    const int tg = g_tgti[token];
    if (tg == -100) { if (threadIdx.x == 0) g_tgt[token] = 0.f; return; }
    const float4* a = reinterpret_cast<const float4*>(input + (size_t)token * KH);
    const float4* w = reinterpret_cast<const float4*>(weight + (size_t)tg * KH);
    float s = 0.f;
    #pragma unroll
    for (int j = 0; j < 4; j++) {
        const int i = threadIdx.x + j * 128;       // 512 float4 total
        float4 av = a[i], wv = w[i];
        s += av.x * wv.x + av.y * wv.y + av.z * wv.z + av.w * wv.w;
    }
    #pragma unroll
    for (int o = 16; o > 0; o >>= 1) s += __shfl_xor_sync(0xffffffffu, s, o);
    __shared__ float ws[4];
    if ((threadIdx.x & 31) == 0) ws[threadIdx.x >> 5] = s;
    __syncthreads();
    if (threadIdx.x == 0)
        g_tgt[token] = ws[0] + ws[1] + ws[2] + ws[3] + bias[tg];
}

// ---------------- fused GEMM + partial softmax ----------------
// 128x128 CTA tile, 4 warps of 64x64, 3-stage cp.async pipeline, 2 CTAs/SM.
__global__ void __launch_bounds__(128, 2) gemm_softmax_kernel(
    const float* __restrict__ bias) {
    extern __shared__ char smem[];
    const uint32_t sbase = smem_u32(smem);
    const int tid = threadIdx.x;
    const int lane = tid & 31;
    const int warp = tid >> 5;
    const int wm = warp >> 1;          // 0..1  (m slice of 64 rows)
    const int wn = warp & 1;           // 0..1  (n slice of 64 cols)
    const int m0 = blockIdx.x * BM;
    const int v0 = blockIdx.y * BN;

    // stage loader: fills slot (it % 3) with K-slice `it`
    auto load_stage = [&](int it) {
        const int st = it % NSTAGE;
        const int k0 = it * BK;
        const uint32_t sA = sbase + st * STG;
        const __half* ab = g_a + (size_t)m0 * KH + k0;
        #pragma unroll
        for (int j = 0; j < 8; j++) {            // 128 rows x 8 segs / 128 thr
            int id = tid + j * 128;
            int row = id >> 3, seg = id & 7;
            cp16(sA + sw128(row * 128 + seg * 16), ab + (size_t)row * KH + seg * 8);
        }
        const uint32_t sB = sA + A_STG;
        const __half* bb = g_w + (size_t)v0 * KH + k0;
        #pragma unroll
        for (int j = 0; j < 8; j++) {
            int id = tid + j * 128;
            int row = id >> 3, seg = id & 7;
            cp16(sB + sw128(row * 128 + seg * 16), bb + (size_t)row * KH + seg * 8);
        }
    };

    load_stage(0); cp_commit();
    load_stage(1); cp_commit();

    float acc[4][8][4];
    #pragma unroll
    for (int mt = 0; mt < 4; mt++)
        #pragma unroll
        for (int nt = 0; nt < 8; nt++)
            #pragma unroll
            for (int r = 0; r < 4; r++) acc[mt][nt][r] = 0.f;

    // per-lane ldmatrix base byte offsets (within tile, before swizzle)
    uint32_t aoff[4], boff[4];
    #pragma unroll
    for (int mt = 0; mt < 4; mt++)
        aoff[mt] = (uint32_t)(wm * 64 + mt * 16 + (lane & 7) + ((lane >> 3) & 1) * 8) * 128
                 + ((lane >> 4) & 1) * 16;
    #pragma unroll
    for (int np = 0; np < 4; np++)      // pair of n8-tiles (16 B-rows)
        boff[np] = (uint32_t)(wn * 64 + np * 16 + ((lane >> 4) & 1) * 8 + (lane & 7)) * 128
                 + ((lane >> 3) & 1) * 16;

    for (int it = 0; it < NIT; ++it) {
        asm volatile("cp.async.wait_group 1;" ::: "memory");
        __syncthreads();
        if (it + 2 < NIT) load_stage(it + 2);
        cp_commit();

        const uint32_t sA = sbase + (it % NSTAGE) * STG;
        const uint32_t sB = sA + A_STG;
        #pragma unroll
        for (int ks = 0; ks < 4; ks++) {
            uint32_t a[4][4], b[4][4];
            #pragma unroll
            for (int mt = 0; mt < 4; mt++) ldsm4(a[mt], sA + sw128(aoff[mt] + ks * 32));
            #pragma unroll
            for (int np = 0; np < 4; np++) ldsm4(b[np], sB + sw128(boff[np] + ks * 32));
            #pragma unroll
            for (int mt = 0; mt < 4; mt++)
                #pragma unroll
                for (int nt = 0; nt < 8; nt++)
                    mma16816(acc[mt][nt], a[mt], b[nt >> 1] + (nt & 1) * 2);
        }
    }

    // ---------------- epilogue: fused partial softmax ----------------
    asm volatile("cp.async.wait_group 0;" ::: "memory");
    __syncthreads();
    float* sbias = reinterpret_cast<float*>(smem);
    sbias[tid] = bias[v0 + tid];
    __syncthreads();

    const int slice = blockIdx.y * 2 + wn;
    const int cbase = wn * 64 + (lane & 3) * 2;      // local col of reg j=0

    #pragma unroll
    for (int mt = 0; mt < 4; mt++) {
        #pragma unroll
        for (int half = 0; half < 2; half++) {
            const int row = wm * 64 + mt * 16 + (lane >> 2) + half * 8;
            const int token = m0 + row;
            float x[16];
            float M = -3.402823466e38f;
            #pragma unroll
            for (int nt = 0; nt < 8; nt++) {
                x[2 * nt]     = acc[mt][nt][2 * half]     + sbias[cbase + nt * 8];
                x[2 * nt + 1] = acc[mt][nt][2 * half + 1] + sbias[cbase + nt * 8 + 1];
                M = fmaxf(M, fmaxf(x[2 * nt], x[2 * nt + 1]));
            }
            M = fmaxf(M, __shfl_xor_sync(0xffffffffu, M, 1));
            M = fmaxf(M, __shfl_xor_sync(0xffffffffu, M, 2));
            float S = 0.f;
            #pragma unroll
            for (int j = 0; j < 16; j++) S += __expf(x[j] - M);
            S += __shfl_xor_sync(0xffffffffu, S, 1);
            S += __shfl_xor_sync(0xffffffffu, S, 2);
            if ((lane & 3) == 0) {
                g_pmax[(size_t)slice * NTOK + token] = M;
                g_psum[(size_t)slice * NTOK + token] = S;
            }
        }
    }
}

// ---------------- per-sequence LSE combine + avg logp ----------------
__global__ void reduce_kernel() {
    __shared__ float rs[512];
    __shared__ float rc[512];
    const int seq = blockIdx.x, t = threadIdx.x;
    const int token = seq * 512 + t;
    const int tg = g_tgti[token];
    float val = 0.f, cnt = 0.f;
    if (tg != -100) {
        float M = -3.402823466e38f, S = 0.f;
        #pragma unroll 4
        for (int sl = 0; sl < NSLICE; sl++) {
            const float mv = g_pmax[(size_t)sl * NTOK + token];
            const float sv = g_psum[(size_t)sl * NTOK + token];
            const float nm = fmaxf(M, mv);
            S = S * __expf(M - nm) + sv * __expf(mv - nm);
            M = nm;
        }
        val = g_tgt[token] - (M + __logf(S));
        cnt = 1.f;
    }
    rs[t] = val; rc[t] = cnt;
    __syncthreads();
    for (int o = 256; o > 0; o >>= 1) {
        if (t < o) { rs[t] += rs[t + o]; rc[t] += rc[t + o]; }
        __syncthreads();
    }
    if (t == 0) g_avg[seq] = rs[0] / fmaxf(rc[0], 1.f);
}

// ---------------- SimPO pair loss ----------------
__global__ void finalize_kernel(float* __restrict__ out) {
    if (threadIdx.x == 0 && blockIdx.x == 0) {
        float loss = 0.f;
        #pragma unroll
        for (int i = 0; i < 4; i++) {
            const float d = 0.1f * (g_avg[i] - g_avg[i + 4]) - 0.5f;
            const float xm = -d;  // -log_sigmoid(d) = softplus(-d)
            loss += (xm > 0.f) ? (xm + log1pf(expf(-xm))) : log1pf(expf(xm));
        }
        out[0] = loss * 0.25f;
    }
}

// ---------------- launch ----------------
extern "C" void kernel_launch(void* const* d_in, const int* in_sizes, int n_in,
                              void* d_out, int out_size) {
    const float* lin_weight = (const float*)d_in[0];       // [V, H]
    const float* input      = (const float*)d_in[1];       // [B, T, H]
    const int*   target_raw = (const int*)d_in[2];         // [B, T] int32 or int64
    const float* bias       = (const float*)d_in[3];       // [V]

    cudaFuncSetAttribute(gemm_softmax_kernel,
                         cudaFuncAttributeMaxDynamicSharedMemorySize, SMEM_BYTES);

    tgt_decode_kernel<<<1, 1024>>>(target_raw);
    cvt_w_kernel<<<(int)((size_t)VSZ * KH / 8 / 256), 256>>>((const float4*)lin_weight);
    cvt_a_kernel<<<(int)((size_t)NTOK * KH / 8 / 256), 256>>>((const float4*)input);
    tgt_kernel<<<NTOK, 128>>>(lin_weight, input, bias);

    dim3 grid(NTOK / BM, NVT);   // x-fastest => 32 M-CTAs share each W tile in L2
    gemm_softmax_kernel<<<grid, 128, SMEM_BYTES>>>(bias);

    reduce_kernel<<<8, 512>>>();
    finalize_kernel<<<1, 32>>>((float*)d_out);
}